// round 10
// baseline (speedup 1.0000x reference)
#include <cuda_runtime.h>

// VDDecoder: 3-layer LSTM stack (H=2,2,1), locked dropout between layers.
// R10: lane-pair role split (even lane = layer1, odd lane = layer2, uniform
// stream; layer3 redundant on both lanes) AND two independent batch elements
// per thread (e0=2p, e1=2p+1) so the two serial dependency chains interleave
// and fill each other's stall cycles. x loads / output stores are float2.
// Masks applied explicitly (weights shared across the thread's 2 elements).

typedef unsigned long long u64;

__device__ __forceinline__ float ftanh(float x) {
    float r; asm("tanh.approx.f32 %0, %1;" : "=f"(r) : "f"(x)); return r;
}
__device__ __forceinline__ u64 fpack(float lo, float hi) {
    u64 d; asm("mov.b64 %0, {%1, %2};" : "=l"(d) : "f"(lo), "f"(hi)); return d;
}
__device__ __forceinline__ u64 fpack2(float v) { return fpack(v, v); }
__device__ __forceinline__ void funpack(u64 v, float& lo, float& hi) {
    asm("mov.b64 {%0, %1}, %2;" : "=f"(lo), "=f"(hi) : "l"(v));
}
__device__ __forceinline__ u64 ffma2(u64 a, u64 b, u64 c) {
    u64 d; asm("fma.rn.f32x2 %0, %1, %2, %3;" : "=l"(d) : "l"(a), "l"(b), "l"(c)); return d;
}

extern "C" __global__ void __launch_bounds__(128, 1)
vdlstm_v6_kernel(const float* __restrict__ x,
                 const float* __restrict__ W1ih, const float* __restrict__ W1hh,
                 const float* __restrict__ b1,   const float* __restrict__ m1,
                 const float* __restrict__ W2ih, const float* __restrict__ W2hh,
                 const float* __restrict__ b2,   const float* __restrict__ m2,
                 const float* __restrict__ W3ih, const float* __restrict__ W3hh,
                 const float* __restrict__ b3,   const float* __restrict__ m3,
                 float* __restrict__ out, int T, int B)
{
    const int gtid = blockIdx.x * blockDim.x + threadIdx.x;
    const int role = gtid & 1;                  // 0 = layer1 lane, 1 = layer2 lane
    const int e0   = 2 * (gtid >> 1);           // elements e0, e0+1
    if (e0 >= B) return;

    // ---- uniform main-LSTM weights (H=2, inputs a0,a1); shared by both elems ----
    u64 Wi0[4], Wi1[4], Wh0[4], Wh1[4], Bb[4];
    if (role == 0) {
#pragma unroll
        for (int p = 0; p < 4; p++) {
            float s = (p == 2) ? 1.0f : 0.5f;
            int r0 = 2 * p, r1 = 2 * p + 1;
            Wi0[p] = fpack(W1ih[r0] * s,          W1ih[r1] * s);
            Wi1[p] = fpack(0.f, 0.f);
            Wh0[p] = fpack(W1hh[2 * r0 + 0] * s,  W1hh[2 * r1 + 0] * s);
            Wh1[p] = fpack(W1hh[2 * r0 + 1] * s,  W1hh[2 * r1 + 1] * s);
            Bb[p]  = fpack(b1[r0] * s,            b1[r1] * s);
        }
    } else {
#pragma unroll
        for (int p = 0; p < 4; p++) {
            float s = (p == 2) ? 1.0f : 0.5f;
            int r0 = 2 * p, r1 = 2 * p + 1;
            Wi0[p] = fpack(W2ih[2 * r0 + 0] * s, W2ih[2 * r1 + 0] * s);
            Wi1[p] = fpack(W2ih[2 * r0 + 1] * s, W2ih[2 * r1 + 1] * s);
            Wh0[p] = fpack(W2hh[2 * r0 + 0] * s, W2hh[2 * r1 + 0] * s);
            Wh1[p] = fpack(W2hh[2 * r0 + 1] * s, W2hh[2 * r1 + 1] * s);
            Bb[p]  = fpack(b2[r0] * s,           b2[r1] * s);
        }
    }

    // ---- layer3 weights (shared; masks NOT folded). pairs A=(i,f), B=(g,o) ----
    u64 P3wi0A = fpack(W3ih[0] * 0.5f, W3ih[2] * 0.5f);
    u64 P3wi1A = fpack(W3ih[1] * 0.5f, W3ih[3] * 0.5f);
    u64 P3whA  = fpack(W3hh[0] * 0.5f, W3hh[1] * 0.5f);
    u64 P3bA   = fpack(b3[0] * 0.5f,   b3[1] * 0.5f);
    u64 P3wi0B = fpack(W3ih[4],        W3ih[6] * 0.5f);
    u64 P3wi1B = fpack(W3ih[5],        W3ih[7] * 0.5f);
    u64 P3whB  = fpack(W3hh[2],        W3hh[3] * 0.5f);
    u64 P3bB   = fpack(b3[2],          b3[3] * 0.5f);

    // ---- per-element masks ----
    float am0[2], am1[2], m20a[2], m21a[2], m30a[2];
#pragma unroll
    for (int k = 0; k < 2; k++) {
        int ek = e0 + k;
        am0[k]  = role ? m1[2 * ek + 0] : 1.0f;   // applied to incoming h1
        am1[k]  = role ? m1[2 * ek + 1] : 1.0f;
        m20a[k] = m2[2 * ek + 0];                 // applied to h2 before layer3
        m21a[k] = m2[2 * ek + 1];
        m30a[k] = m3[ek];
    }

    // ---- per-element state ----
    float hm0a[2] = {0.f, 0.f}, hm1a[2] = {0.f, 0.f};
    float cm0a[2] = {0.f, 0.f}, cm1a[2] = {0.f, 0.f};
    float h3a[2]  = {0.f, 0.f}, c3a[2]  = {0.f, 0.f};
    float p20a[2] = {0.f, 0.f}, p21a[2] = {0.f, 0.f};
    float rin0a[2] = {0.f, 0.f}, rin1a[2] = {0.f, 0.f};

    // prologue-only per-element main step
    auto mainStepK = [&](int k, float a0, float a1,
                         float& nh0, float& nh1, float& nc0, float& nc1) {
        u64 a0b = fpack2(a0), a1b = fpack2(a1);
        u64 h0b = fpack2(hm0a[k]), h1b = fpack2(hm1a[k]);
        u64 gI = ffma2(a0b, Wi0[0], ffma2(a1b, Wi1[0], ffma2(h0b, Wh0[0], ffma2(h1b, Wh1[0], Bb[0]))));
        u64 gF = ffma2(a0b, Wi0[1], ffma2(a1b, Wi1[1], ffma2(h0b, Wh0[1], ffma2(h1b, Wh1[1], Bb[1]))));
        u64 gG = ffma2(a0b, Wi0[2], ffma2(a1b, Wi1[2], ffma2(h0b, Wh0[2], ffma2(h1b, Wh1[2], Bb[2]))));
        u64 gO = ffma2(a0b, Wi0[3], ffma2(a1b, Wi1[3], ffma2(h0b, Wh0[3], ffma2(h1b, Wh1[3], Bb[3]))));
        float gi0, gi1, gf0, gf1, gg0, gg1, go0, go1;
        funpack(gI, gi0, gi1); funpack(gF, gf0, gf1);
        funpack(gG, gg0, gg1); funpack(gO, go0, go1);
        float i0 = fmaf(ftanh(gi0), 0.5f, 0.5f), i1 = fmaf(ftanh(gi1), 0.5f, 0.5f);
        float f0 = fmaf(ftanh(gf0), 0.5f, 0.5f), f1 = fmaf(ftanh(gf1), 0.5f, 0.5f);
        float t0 = ftanh(gg0), t1 = ftanh(gg1);
        float o0 = fmaf(ftanh(go0), 0.5f, 0.5f), o1 = fmaf(ftanh(go1), 0.5f, 0.5f);
        nc0 = fmaf(f0, cm0a[k], i0 * t0);
        nc1 = fmaf(f1, cm1a[k], i1 * t1);
        nh0 = o0 * ftanh(nc0);
        nh1 = o1 * ftanh(nc1);
    };

    const float* xp = x + e0;
    float* op = out + e0;
    const long long Bs = (long long)B;
    const unsigned FULL = 0xffffffffu;

    // ---- prologue u = 0 ----
    {
        float2 x0 = *(const float2*)(xp);
#pragma unroll
        for (int k = 0; k < 2; k++) {
            float xk = k ? x0.y : x0.x;
            float a0 = (role ? rin0a[k] : xk) * am0[k];
            float a1 = rin1a[k] * am1[k];
            float nh0, nh1, nc0, nc1;
            mainStepK(k, a0, a1, nh0, nh1, nc0, nc1);
            if (role == 0) { hm0a[k] = nh0; hm1a[k] = nh1; cm0a[k] = nc0; cm1a[k] = nc1; }
        }
#pragma unroll
        for (int k = 0; k < 2; k++) {
            rin0a[k] = __shfl_xor_sync(FULL, hm0a[k], 1);
            rin1a[k] = __shfl_xor_sync(FULL, hm1a[k], 1);
        }
    }
    // ---- prologue u = 1 ----
    {
        float2 x1 = *(const float2*)(xp + Bs);
#pragma unroll
        for (int k = 0; k < 2; k++) {
            float xk = k ? x1.y : x1.x;
            float a0 = (role ? rin0a[k] : xk) * am0[k];
            float a1 = rin1a[k] * am1[k];
            float nh0, nh1, nc0, nc1;
            mainStepK(k, a0, a1, nh0, nh1, nc0, nc1);
            hm0a[k] = nh0; hm1a[k] = nh1; cm0a[k] = nc0; cm1a[k] = nc1;
        }
#pragma unroll
        for (int k = 0; k < 2; k++) {
            float s0 = __shfl_xor_sync(FULL, hm0a[k], 1);
            float s1 = __shfl_xor_sync(FULL, hm1a[k], 1);
            p20a[k] = role ? hm0a[k] : s0;    // h2(0)
            p21a[k] = role ? hm1a[k] : s1;
            rin0a[k] = s0; rin1a[k] = s1;
        }
    }

    // ---- steady state: u = 2 .. T+1 ----
    float2 xa = *(const float2*)(xp + 2 * Bs);
    float2 xb = *(const float2*)(xp + 3 * Bs);
    float2 xc = *(const float2*)(xp + 4 * Bs);
    float2 xd = *(const float2*)(xp + 5 * Bs);

#define V6_ITER(XREG, OFF)                                                     \
    {                                                                          \
        const int uu = u + (OFF);                                              \
        int nidx = (uu + 4 < T) ? (uu + 4) : (T - 1);                          \
        float2 nx = *(const float2*)(xp + (long long)nidx * Bs);               \
        /* Phase A: all gate pre-activations, both elements */                 \
        u64 gI[2], gF[2], gG[2], gO[2], gA[2], gB[2];                          \
        _Pragma("unroll")                                                      \
        for (int k = 0; k < 2; k++) {                                          \
            float xk = k ? XREG.y : XREG.x;                                    \
            float a0 = (role ? rin0a[k] : xk) * am0[k];                        \
            float a1 = rin1a[k] * am1[k];                                      \
            float q0 = p20a[k] * m20a[k], q1 = p21a[k] * m21a[k];              \
            u64 a0b = fpack2(a0), a1b = fpack2(a1);                            \
            u64 h0b = fpack2(hm0a[k]), h1b = fpack2(hm1a[k]);                  \
            u64 q0b = fpack2(q0), q1b = fpack2(q1), h3b = fpack2(h3a[k]);      \
            gI[k] = ffma2(a0b, Wi0[0], ffma2(a1b, Wi1[0], ffma2(h0b, Wh0[0], ffma2(h1b, Wh1[0], Bb[0])))); \
            gF[k] = ffma2(a0b, Wi0[1], ffma2(a1b, Wi1[1], ffma2(h0b, Wh0[1], ffma2(h1b, Wh1[1], Bb[1])))); \
            gG[k] = ffma2(a0b, Wi0[2], ffma2(a1b, Wi1[2], ffma2(h0b, Wh0[2], ffma2(h1b, Wh1[2], Bb[2])))); \
            gO[k] = ffma2(a0b, Wi0[3], ffma2(a1b, Wi1[3], ffma2(h0b, Wh0[3], ffma2(h1b, Wh1[3], Bb[3])))); \
            gA[k] = ffma2(q0b, P3wi0A, ffma2(q1b, P3wi1A, ffma2(h3b, P3whA, P3bA))); \
            gB[k] = ffma2(q0b, P3wi0B, ffma2(q1b, P3wi1B, ffma2(h3b, P3whB, P3bB))); \
        }                                                                      \
        /* Phase B: all 24 gate tanhs */                                       \
        float ti0[2], ti1[2], tf0[2], tf1[2], tg0[2], tg1[2], to0[2], to1[2];  \
        float tvi[2], tvf[2], tvg[2], tvo[2];                                  \
        _Pragma("unroll")                                                      \
        for (int k = 0; k < 2; k++) {                                          \
            float v0, v1;                                                      \
            funpack(gI[k], v0, v1); ti0[k] = ftanh(v0); ti1[k] = ftanh(v1);    \
            funpack(gF[k], v0, v1); tf0[k] = ftanh(v0); tf1[k] = ftanh(v1);    \
            funpack(gG[k], v0, v1); tg0[k] = ftanh(v0); tg1[k] = ftanh(v1);    \
            funpack(gO[k], v0, v1); to0[k] = ftanh(v0); to1[k] = ftanh(v1);    \
            funpack(gA[k], v0, v1); tvi[k] = ftanh(v0); tvf[k] = ftanh(v1);    \
            funpack(gB[k], v0, v1); tvg[k] = ftanh(v0); tvo[k] = ftanh(v1);    \
        }                                                                      \
        /* Phase C: sigmoids + cell updates */                                 \
        float o0a[2], o1a[2], soa[2];                                          \
        _Pragma("unroll")                                                      \
        for (int k = 0; k < 2; k++) {                                          \
            float i0 = fmaf(ti0[k], 0.5f, 0.5f), i1 = fmaf(ti1[k], 0.5f, 0.5f); \
            float f0 = fmaf(tf0[k], 0.5f, 0.5f), f1 = fmaf(tf1[k], 0.5f, 0.5f); \
            o0a[k] = fmaf(to0[k], 0.5f, 0.5f); o1a[k] = fmaf(to1[k], 0.5f, 0.5f); \
            float si = fmaf(tvi[k], 0.5f, 0.5f), sf = fmaf(tvf[k], 0.5f, 0.5f); \
            soa[k] = fmaf(tvo[k], 0.5f, 0.5f);                                 \
            cm0a[k] = fmaf(f0, cm0a[k], i0 * tg0[k]);                          \
            cm1a[k] = fmaf(f1, cm1a[k], i1 * tg1[k]);                          \
            c3a[k]  = fmaf(sf, c3a[k], si * tvg[k]);                           \
        }                                                                      \
        /* Phase D: cell tanhs */                                              \
        float tc0[2], tc1[2], tc3[2];                                          \
        _Pragma("unroll")                                                      \
        for (int k = 0; k < 2; k++) {                                          \
            tc0[k] = ftanh(cm0a[k]); tc1[k] = ftanh(cm1a[k]); tc3[k] = ftanh(c3a[k]); \
        }                                                                      \
        /* Phase E: h, shfl, store, rotate */                                  \
        _Pragma("unroll")                                                      \
        for (int k = 0; k < 2; k++) {                                          \
            hm0a[k] = o0a[k] * tc0[k];                                         \
            hm1a[k] = o1a[k] * tc1[k];                                         \
            h3a[k]  = soa[k] * tc3[k];                                         \
        }                                                                      \
        float s00 = __shfl_xor_sync(FULL, hm0a[0], 1);                         \
        float s10 = __shfl_xor_sync(FULL, hm1a[0], 1);                         \
        float s01 = __shfl_xor_sync(FULL, hm0a[1], 1);                         \
        float s11 = __shfl_xor_sync(FULL, hm1a[1], 1);                         \
        if (role == 0) {                                                       \
            float2 y; y.x = h3a[0] * m30a[0]; y.y = h3a[1] * m30a[1];          \
            *(float2*)(op + (long long)(uu - 2) * Bs) = y;                     \
        }                                                                      \
        p20a[0] = role ? hm0a[0] : s00;  p21a[0] = role ? hm1a[0] : s10;       \
        p20a[1] = role ? hm0a[1] : s01;  p21a[1] = role ? hm1a[1] : s11;       \
        rin0a[0] = s00; rin1a[0] = s10;                                        \
        rin0a[1] = s01; rin1a[1] = s11;                                        \
        XREG = nx;                                                             \
    }

    int u = 2;
    const int UEND = T + 2;                 // exclusive; emits rows 0..T-1
    for (; u + 3 < UEND; u += 4) {
        V6_ITER(xa, 0)
        V6_ITER(xb, 1)
        V6_ITER(xc, 2)
        V6_ITER(xd, 3)
    }
    for (; u < UEND; ++u) {
        V6_ITER(xa, 0)
        xa = xb; xb = xc; xc = xd;
    }
#undef V6_ITER
}

extern "C" void kernel_launch(void* const* d_in, const int* in_sizes, int n_in,
                              void* d_out, int out_size)
{
    const float* x    = (const float*)d_in[0];
    const float* W1ih = (const float*)d_in[1];
    const float* W1hh = (const float*)d_in[2];
    const float* b1   = (const float*)d_in[3];
    const float* m1   = (const float*)d_in[4];
    const float* W2ih = (const float*)d_in[5];
    const float* W2hh = (const float*)d_in[6];
    const float* b2   = (const float*)d_in[7];
    const float* m2   = (const float*)d_in[8];
    const float* W3ih = (const float*)d_in[9];
    const float* W3hh = (const float*)d_in[10];
    const float* b3   = (const float*)d_in[11];
    const float* m3   = (const float*)d_in[12];

    int B = in_sizes[12];            // m3 is [B]
    int T = in_sizes[0] / B;         // x is [T, B, 1]

    // 2 roles x (B/2 element-pairs) = B threads total; 2 elements per thread.
    int threads = 128;
    int blocks = (B + threads - 1) / threads;
    vdlstm_v6_kernel<<<blocks, threads>>>(x, W1ih, W1hh, b1, m1,
                                          W2ih, W2hh, b2, m2,
                                          W3ih, W3hh, b3, m3,
                                          (float*)d_out, T, B);
}

// round 11
// speedup vs baseline: 1.4050x; 1.4050x over previous
#include <cuda_runtime.h>

// VDDecoder: 3-layer LSTM stack (H=2,2,1), locked dropout between layers.
// R11: THREE-role lane split. Lanes work in triples (role0=layer1,
// role1=layer2, role2=layer3-padded-to-H2), all running ONE uniform LSTM step;
// h passed down the triple with __shfl_up(1), hidden by the 1-step stagger
// (role r processes time u-r). Layer3's second hidden unit is a zero-weight
// dummy (decays to 0). 10 tanh/lane. 10 elements per warp (lanes 30,31 idle,
// clamped). f32x2 packed gates; tanh.approx; sigmoid rows 0.5-prescaled.

typedef unsigned long long u64;

__device__ __forceinline__ float ftanh(float x) {
    float r; asm("tanh.approx.f32 %0, %1;" : "=f"(r) : "f"(x)); return r;
}
__device__ __forceinline__ u64 fpack(float lo, float hi) {
    u64 d; asm("mov.b64 %0, {%1, %2};" : "=l"(d) : "f"(lo), "f"(hi)); return d;
}
__device__ __forceinline__ u64 fpack2(float v) { return fpack(v, v); }
__device__ __forceinline__ void funpack(u64 v, float& lo, float& hi) {
    asm("mov.b64 {%0, %1}, %2;" : "=f"(lo), "=f"(hi) : "l"(v));
}
__device__ __forceinline__ u64 ffma2(u64 a, u64 b, u64 c) {
    u64 d; asm("fma.rn.f32x2 %0, %1, %2, %3;" : "=l"(d) : "l"(a), "l"(b), "l"(c)); return d;
}

extern "C" __global__ void __launch_bounds__(128, 1)
vdlstm_v7_kernel(const float* __restrict__ x,
                 const float* __restrict__ W1ih, const float* __restrict__ W1hh,
                 const float* __restrict__ b1,   const float* __restrict__ m1,
                 const float* __restrict__ W2ih, const float* __restrict__ W2hh,
                 const float* __restrict__ b2,   const float* __restrict__ m2,
                 const float* __restrict__ W3ih, const float* __restrict__ W3hh,
                 const float* __restrict__ b3,   const float* __restrict__ m3,
                 float* __restrict__ out, int T, int B)
{
    const int lane = threadIdx.x & 31;
    const int gw   = blockIdx.x * (blockDim.x >> 5) + (threadIdx.x >> 5);  // global warp
    const int role = lane % 3;                       // 0:L1  1:L2  2:L3
    int e = gw * 10 + lane / 3;                      // lanes 30,31 -> e = gw*10+10 (clamped)
    if (e > B - 1) e = B - 1;

    // ---- uniform weights (H=2, 2 inputs a0,a1); values per role ----
    // gate-pair p = torch rows (2p,2p+1): p0=i p1=f p2=g(tanh,unscaled) p3=o
    u64 Wi0[4], Wi1[4], Wh0[4], Wh1[4], Bb[4];
    if (role == 0) {            // layer1: a0 = x, a1 dead (zero weights)
#pragma unroll
        for (int p = 0; p < 4; p++) {
            float s = (p == 2) ? 1.0f : 0.5f;
            int r0 = 2 * p, r1 = 2 * p + 1;
            Wi0[p] = fpack(W1ih[r0] * s,         W1ih[r1] * s);
            Wi1[p] = fpack(0.f, 0.f);
            Wh0[p] = fpack(W1hh[2 * r0 + 0] * s, W1hh[2 * r1 + 0] * s);
            Wh1[p] = fpack(W1hh[2 * r0 + 1] * s, W1hh[2 * r1 + 1] * s);
            Bb[p]  = fpack(b1[r0] * s,           b1[r1] * s);
        }
    } else if (role == 1) {     // layer2: a = h1 (m1 applied on input)
#pragma unroll
        for (int p = 0; p < 4; p++) {
            float s = (p == 2) ? 1.0f : 0.5f;
            int r0 = 2 * p, r1 = 2 * p + 1;
            Wi0[p] = fpack(W2ih[2 * r0 + 0] * s, W2ih[2 * r1 + 0] * s);
            Wi1[p] = fpack(W2ih[2 * r0 + 1] * s, W2ih[2 * r1 + 1] * s);
            Wh0[p] = fpack(W2hh[2 * r0 + 0] * s, W2hh[2 * r1 + 0] * s);
            Wh1[p] = fpack(W2hh[2 * r0 + 1] * s, W2hh[2 * r1 + 1] * s);
            Bb[p]  = fpack(b2[r0] * s,           b2[r1] * s);
        }
    } else {                    // layer3 padded to H=2: hi slot of each pair dead
#pragma unroll
        for (int p = 0; p < 4; p++) {
            float s = (p == 2) ? 1.0f : 0.5f;
            Wi0[p] = fpack(W3ih[2 * p + 0] * s, 0.f);
            Wi1[p] = fpack(W3ih[2 * p + 1] * s, 0.f);
            Wh0[p] = fpack(W3hh[p] * s,         0.f);   // h3 = hm0; hm1 dummy
            Wh1[p] = fpack(0.f, 0.f);
            Bb[p]  = fpack(b3[p] * s,           0.f);
        }
    }

    // ---- input masks for this role (applied to incoming h pair) ----
    float am0 = 1.f, am1 = 1.f;
    if (role == 1) { am0 = m1[2 * e + 0]; am1 = m1[2 * e + 1]; }
    if (role == 2) { am0 = m2[2 * e + 0]; am1 = m2[2 * e + 1]; }
    const float m30 = m3[e];

    // ---- state ----
    float hm0 = 0.f, hm1 = 0.f, cm0 = 0.f, cm1 = 0.f;
    float rin0 = 0.f, rin1 = 0.f;          // h pair received from role-1 lane

    const float* xp = x + e;
    float* op = out + e;
    const long long Bs = (long long)B;
    const unsigned FULL = 0xffffffffu;

    // one uniform step; returns new h/c without committing
    auto stepU = [&](float a0, float a1,
                     float& nh0, float& nh1, float& nc0, float& nc1) {
        u64 a0b = fpack2(a0), a1b = fpack2(a1);
        u64 h0b = fpack2(hm0), h1b = fpack2(hm1);
        u64 gI = ffma2(a0b, Wi0[0], ffma2(a1b, Wi1[0], ffma2(h0b, Wh0[0], ffma2(h1b, Wh1[0], Bb[0]))));
        u64 gF = ffma2(a0b, Wi0[1], ffma2(a1b, Wi1[1], ffma2(h0b, Wh0[1], ffma2(h1b, Wh1[1], Bb[1]))));
        u64 gG = ffma2(a0b, Wi0[2], ffma2(a1b, Wi1[2], ffma2(h0b, Wh0[2], ffma2(h1b, Wh1[2], Bb[2]))));
        u64 gO = ffma2(a0b, Wi0[3], ffma2(a1b, Wi1[3], ffma2(h0b, Wh0[3], ffma2(h1b, Wh1[3], Bb[3]))));
        float gi0, gi1, gf0, gf1, gg0, gg1, go0, go1;
        funpack(gI, gi0, gi1); funpack(gF, gf0, gf1);
        funpack(gG, gg0, gg1); funpack(gO, go0, go1);
        float ti0 = ftanh(gi0), ti1 = ftanh(gi1);
        float tf0 = ftanh(gf0), tf1 = ftanh(gf1);
        float tg0 = ftanh(gg0), tg1 = ftanh(gg1);
        float to0 = ftanh(go0), to1 = ftanh(go1);
        float i0 = fmaf(ti0, 0.5f, 0.5f), i1 = fmaf(ti1, 0.5f, 0.5f);
        float f0 = fmaf(tf0, 0.5f, 0.5f), f1 = fmaf(tf1, 0.5f, 0.5f);
        float o0 = fmaf(to0, 0.5f, 0.5f), o1 = fmaf(to1, 0.5f, 0.5f);
        nc0 = fmaf(f0, cm0, i0 * tg0);
        nc1 = fmaf(f1, cm1, i1 * tg1);
        nh0 = o0 * ftanh(nc0);
        nh1 = o1 * ftanh(nc1);
    };

    // ---- prologue u = 0: only role0 commits ----
    {
        float xk = xp[0];
        float a0 = (role == 0) ? xk : rin0 * am0;
        float a1 = rin1 * am1;
        float nh0, nh1, nc0, nc1;
        stepU(a0, a1, nh0, nh1, nc0, nc1);
        if (role == 0) { hm0 = nh0; hm1 = nh1; cm0 = nc0; cm1 = nc1; }
        rin0 = __shfl_up_sync(FULL, hm0, 1);
        rin1 = __shfl_up_sync(FULL, hm1, 1);
    }
    // ---- prologue u = 1: roles 0,1 commit ----
    {
        float xk = xp[Bs];
        float a0 = (role == 0) ? xk : rin0 * am0;
        float a1 = rin1 * am1;
        float nh0, nh1, nc0, nc1;
        stepU(a0, a1, nh0, nh1, nc0, nc1);
        if (role <= 1) { hm0 = nh0; hm1 = nh1; cm0 = nc0; cm1 = nc1; }
        rin0 = __shfl_up_sync(FULL, hm0, 1);
        rin1 = __shfl_up_sync(FULL, hm1, 1);
    }

    // ---- steady state: u = 2 .. T+1; role r works on time u-r; role2 stores u-2 ----
    float xa = xp[2 * Bs], xb = xp[3 * Bs], xc = xp[4 * Bs], xd = xp[5 * Bs];

#define V7_ITER(XREG, OFF)                                                     \
    {                                                                          \
        const int uu = u + (OFF);                                              \
        int nidx = (uu + 4 < T) ? (uu + 4) : (T - 1);                          \
        float nx = xp[(long long)nidx * Bs];                                   \
        float a0 = (role == 0) ? XREG : rin0 * am0;                            \
        float a1 = rin1 * am1;                                                 \
        float nh0, nh1, nc0, nc1;                                              \
        stepU(a0, a1, nh0, nh1, nc0, nc1);                                     \
        hm0 = nh0; hm1 = nh1; cm0 = nc0; cm1 = nc1;                            \
        rin0 = __shfl_up_sync(FULL, hm0, 1);                                   \
        rin1 = __shfl_up_sync(FULL, hm1, 1);                                   \
        if (role == 2) op[(long long)(uu - 2) * Bs] = hm0 * m30;               \
        XREG = nx;                                                             \
    }

    int u = 2;
    const int UEND = T + 2;                 // exclusive; emits rows 0..T-1
    for (; u + 3 < UEND; u += 4) {
        V7_ITER(xa, 0)
        V7_ITER(xb, 1)
        V7_ITER(xc, 2)
        V7_ITER(xd, 3)
    }
    for (; u < UEND; ++u) {
        V7_ITER(xa, 0)
        xa = xb; xb = xc; xc = xd;
    }
#undef V7_ITER
}

extern "C" void kernel_launch(void* const* d_in, const int* in_sizes, int n_in,
                              void* d_out, int out_size)
{
    const float* x    = (const float*)d_in[0];
    const float* W1ih = (const float*)d_in[1];
    const float* W1hh = (const float*)d_in[2];
    const float* b1   = (const float*)d_in[3];
    const float* m1   = (const float*)d_in[4];
    const float* W2ih = (const float*)d_in[5];
    const float* W2hh = (const float*)d_in[6];
    const float* b2   = (const float*)d_in[7];
    const float* m2   = (const float*)d_in[8];
    const float* W3ih = (const float*)d_in[9];
    const float* W3hh = (const float*)d_in[10];
    const float* b3   = (const float*)d_in[11];
    const float* m3   = (const float*)d_in[12];

    int B = in_sizes[12];            // m3 is [B]
    int T = in_sizes[0] / B;         // x is [T, B, 1]

    // 10 elements per warp (lanes 0..29 in triples; 30,31 idle/clamped).
    int warps  = (B + 9) / 10;
    int threads = 128;               // 4 warps per block
    int blocks = (warps + 3) / 4;
    vdlstm_v7_kernel<<<blocks, threads>>>(x, W1ih, W1hh, b1, m1,
                                          W2ih, W2hh, b2, m2,
                                          W3ih, W3hh, b3, m3,
                                          (float*)d_out, T, B);
}

// round 12
// speedup vs baseline: 1.6011x; 1.1396x over previous
#include <cuda_runtime.h>

// VDDecoder: 3-layer LSTM stack (H=2,2,1), locked dropout between layers.
// R12: ONE hidden unit per lane. 5-lane groups per element:
//   sub0=L1u0, sub1=L1u1, sub2=L2u0, sub3=L2u1, sub4=L3.
// All lanes run the identical scalar step (4 gates x 4 ffma, 4 gate tanh,
// cell update, cell tanh) = 5 MUFU/lane. Exchange via 3 shfl.idx with
// precomputed source lanes: sibling h (intra-layer) + prev-layer h pair
// (1-step stagger per layer hop: layer l processes time u-l).
// 6 elements per warp (lanes 30,31 run as clamped extras; no stores).

__device__ __forceinline__ float ftanh(float x) {
    float r; asm("tanh.approx.f32 %0, %1;" : "=f"(r) : "f"(x)); return r;
}

extern "C" __global__ void __launch_bounds__(128, 1)
vdlstm_v8_kernel(const float* __restrict__ x,
                 const float* __restrict__ W1ih, const float* __restrict__ W1hh,
                 const float* __restrict__ b1,   const float* __restrict__ m1,
                 const float* __restrict__ W2ih, const float* __restrict__ W2hh,
                 const float* __restrict__ b2,   const float* __restrict__ m2,
                 const float* __restrict__ W3ih, const float* __restrict__ W3hh,
                 const float* __restrict__ b3,   const float* __restrict__ m3,
                 float* __restrict__ out, int T, int B)
{
    const int lane = threadIdx.x & 31;
    const int gw   = blockIdx.x * (blockDim.x >> 5) + (threadIdx.x >> 5);
    const int grp  = lane / 5;                  // group within warp (0..6; grp 6 = lanes 30,31)
    const int sub  = lane - grp * 5;            // 0..4 role within group
    const int base = grp * 5;                   // group base lane
    int e = gw * 6 + grp;                       // element (grp 6 / overflow clamped)
    if (e > B - 1) e = B - 1;

    // role decode
    const int layer = (sub <= 1) ? 0 : (sub <= 3) ? 1 : 2;
    const int unit  = (sub == 1 || sub == 3) ? 1 : 0;

    // shfl source lanes
    const int sibsrc = (sub == 4) ? lane : (base + (sub ^ 1));
    const int p0src  = (layer == 2) ? (base + 2) : base;       // prev-layer h0
    const int p1src  = (layer == 2) ? (base + 3) : (base + 1); // prev-layer h1

    // ---- per-lane scalar weights: 4 gates (q: 0=i 1=f 2=g 3=o) ----
    float wa0[4], wa1[4], who[4], whs[4], bq[4];
#pragma unroll
    for (int q = 0; q < 4; q++) {
        float s = (q == 2) ? 1.0f : 0.5f;
        if (layer == 0) {
            int row = 2 * q + unit;
            wa0[q] = W1ih[row] * s;
            wa1[q] = 0.f;
            who[q] = W1hh[2 * row + unit] * s;
            whs[q] = W1hh[2 * row + (1 - unit)] * s;
            bq[q]  = b1[row] * s;
        } else if (layer == 1) {
            int row = 2 * q + unit;
            wa0[q] = W2ih[2 * row + 0] * s;
            wa1[q] = W2ih[2 * row + 1] * s;
            who[q] = W2hh[2 * row + unit] * s;
            whs[q] = W2hh[2 * row + (1 - unit)] * s;
            bq[q]  = b2[row] * s;
        } else {
            wa0[q] = W3ih[2 * q + 0] * s;
            wa1[q] = W3ih[2 * q + 1] * s;
            who[q] = W3hh[q] * s;
            whs[q] = 0.f;
            bq[q]  = b3[q] * s;
        }
    }

    // input mask for this lane's layer (applied to incoming prev-layer h pair)
    float am0 = 1.f, am1 = 1.f;
    if (layer == 1) { am0 = m1[2 * e + 0]; am1 = m1[2 * e + 1]; }
    if (layer == 2) { am0 = m2[2 * e + 0]; am1 = m2[2 * e + 1]; }
    const float m30 = m3[e];

    // ---- state ----
    float h = 0.f, c = 0.f;          // own unit
    float hs = 0.f;                  // sibling unit's h (same layer, same time)
    float rin0 = 0.f, rin1 = 0.f;    // prev-layer h pair (staggered)

    const float* xp = x + e;
    float* op = out + e;
    const long long Bs = (long long)B;
    const unsigned FULL = 0xffffffffu;

    // uniform scalar step -> (nh, nc)
    auto stepU = [&](float a0, float a1, float& nh, float& nc) {
        float g0 = fmaf(a0, wa0[0], fmaf(a1, wa1[0], fmaf(h, who[0], fmaf(hs, whs[0], bq[0]))));
        float g1 = fmaf(a0, wa0[1], fmaf(a1, wa1[1], fmaf(h, who[1], fmaf(hs, whs[1], bq[1]))));
        float g2 = fmaf(a0, wa0[2], fmaf(a1, wa1[2], fmaf(h, who[2], fmaf(hs, whs[2], bq[2]))));
        float g3 = fmaf(a0, wa0[3], fmaf(a1, wa1[3], fmaf(h, who[3], fmaf(hs, whs[3], bq[3]))));
        float t0 = ftanh(g0), t1 = ftanh(g1), t2 = ftanh(g2), t3 = ftanh(g3);
        float ig = fmaf(t0, 0.5f, 0.5f);
        float fg = fmaf(t1, 0.5f, 0.5f);
        float og = fmaf(t3, 0.5f, 0.5f);
        nc = fmaf(fg, c, ig * t2);
        nh = og * ftanh(nc);
    };

    // exchange helper: updates hs / rin0 / rin1 from freshly committed h
    auto exch = [&]() {
        float s_sib = __shfl_sync(FULL, h, sibsrc);
        float s_p0  = __shfl_sync(FULL, h, p0src);
        float s_p1  = __shfl_sync(FULL, h, p1src);
        hs = s_sib;
        rin0 = s_p0;
        rin1 = s_p1;
    };

    // ---- prologue u = 0: only layer-0 lanes commit ----
    {
        float xk = xp[0];
        float a0 = (layer == 0) ? xk : rin0 * am0;
        float a1 = rin1 * am1;
        float nh, nc;
        stepU(a0, a1, nh, nc);
        if (layer == 0) { h = nh; c = nc; }
        exch();
    }
    // ---- prologue u = 1: layers 0,1 commit ----
    {
        float xk = xp[Bs];
        float a0 = (layer == 0) ? xk : rin0 * am0;
        float a1 = rin1 * am1;
        float nh, nc;
        stepU(a0, a1, nh, nc);
        if (layer <= 1) { h = nh; c = nc; }
        exch();
    }

    // ---- steady state: u = 2 .. T+1; layer l processes time u-l; L3 stores u-2 ----
    float xa = xp[2 * Bs], xb = xp[3 * Bs], xc = xp[4 * Bs], xd = xp[5 * Bs];

#define V8_ITER(XREG, OFF)                                                     \
    {                                                                          \
        const int uu = u + (OFF);                                              \
        int nidx = (uu + 4 < T) ? (uu + 4) : (T - 1);                          \
        float nx = xp[(long long)nidx * Bs];                                   \
        float a0 = (layer == 0) ? XREG : rin0 * am0;                           \
        float a1 = rin1 * am1;                                                 \
        float nh, nc;                                                          \
        stepU(a0, a1, nh, nc);                                                 \
        h = nh; c = nc;                                                        \
        exch();                                                                \
        if (sub == 4) op[(long long)(uu - 2) * Bs] = h * m30;                  \
        XREG = nx;                                                             \
    }

    int u = 2;
    const int UEND = T + 2;                 // exclusive; emits rows 0..T-1
    for (; u + 3 < UEND; u += 4) {
        V8_ITER(xa, 0)
        V8_ITER(xb, 1)
        V8_ITER(xc, 2)
        V8_ITER(xd, 3)
    }
    for (; u < UEND; ++u) {
        V8_ITER(xa, 0)
        xa = xb; xb = xc; xc = xd;
    }
#undef V8_ITER
}

extern "C" void kernel_launch(void* const* d_in, const int* in_sizes, int n_in,
                              void* d_out, int out_size)
{
    const float* x    = (const float*)d_in[0];
    const float* W1ih = (const float*)d_in[1];
    const float* W1hh = (const float*)d_in[2];
    const float* b1   = (const float*)d_in[3];
    const float* m1   = (const float*)d_in[4];
    const float* W2ih = (const float*)d_in[5];
    const float* W2hh = (const float*)d_in[6];
    const float* b2   = (const float*)d_in[7];
    const float* m2   = (const float*)d_in[8];
    const float* W3ih = (const float*)d_in[9];
    const float* W3hh = (const float*)d_in[10];
    const float* b3   = (const float*)d_in[11];
    const float* m3   = (const float*)d_in[12];

    int B = in_sizes[12];            // m3 is [B]
    int T = in_sizes[0] / B;         // x is [T, B, 1]

    // 6 elements per warp (5 lanes each; lanes 30,31 clamped extras).
    int warps   = (B + 5) / 6;
    int threads = 128;               // 4 warps per block
    int blocks  = (warps + 3) / 4;
    vdlstm_v8_kernel<<<blocks, threads>>>(x, W1ih, W1hh, b1, m1,
                                          W2ih, W2hh, b2, m2,
                                          W3ih, W3hh, b3, m3,
                                          (float*)d_out, T, B);
}

// round 13
// speedup vs baseline: 1.6754x; 1.0465x over previous
#include <cuda_runtime.h>

// VDDecoder: 3-layer LSTM stack (H=2,2,1), locked dropout between layers.
// R13 = R12 (one hidden unit per lane; 5-lane groups: L1u0,L1u1,L2u0,L2u1,L3;
// uniform scalar step, 5 MUFU/lane, 3 shfl exchange, 1-step stagger/layer)
// + strength-reduced addressing (pointer-bumped prefetch & store),
// + split main/tail loops (no clamp logic in the hot loop),
// + gate fmaf ordering with shfl-dependent operands outermost.

__device__ __forceinline__ float ftanh(float x) {
    float r; asm("tanh.approx.f32 %0, %1;" : "=f"(r) : "f"(x)); return r;
}

extern "C" __global__ void __launch_bounds__(128, 1)
vdlstm_v9_kernel(const float* __restrict__ x,
                 const float* __restrict__ W1ih, const float* __restrict__ W1hh,
                 const float* __restrict__ b1,   const float* __restrict__ m1,
                 const float* __restrict__ W2ih, const float* __restrict__ W2hh,
                 const float* __restrict__ b2,   const float* __restrict__ m2,
                 const float* __restrict__ W3ih, const float* __restrict__ W3hh,
                 const float* __restrict__ b3,   const float* __restrict__ m3,
                 float* __restrict__ out, int T, int B)
{
    const int lane = threadIdx.x & 31;
    const int gw   = blockIdx.x * (blockDim.x >> 5) + (threadIdx.x >> 5);
    const int grp  = lane / 5;                  // 0..6 (grp 6 = lanes 30,31)
    const int sub  = lane - grp * 5;            // 0..4 role
    const int base = grp * 5;
    int e = gw * 6 + grp;
    if (e > B - 1) e = B - 1;

    const int layer = (sub <= 1) ? 0 : (sub <= 3) ? 1 : 2;
    const int unit  = (sub == 1 || sub == 3) ? 1 : 0;

    const int sibsrc = (sub == 4) ? lane : (base + (sub ^ 1));
    const int p0src  = (layer == 2) ? (base + 2) : base;
    const int p1src  = (layer == 2) ? (base + 3) : (base + 1);

    // ---- per-lane scalar weights: 4 gates (q: 0=i 1=f 2=g 3=o) ----
    float wa0[4], wa1[4], who[4], whs[4], bq[4];
#pragma unroll
    for (int q = 0; q < 4; q++) {
        float s = (q == 2) ? 1.0f : 0.5f;
        if (layer == 0) {
            int row = 2 * q + unit;
            wa0[q] = W1ih[row] * s;
            wa1[q] = 0.f;
            who[q] = W1hh[2 * row + unit] * s;
            whs[q] = W1hh[2 * row + (1 - unit)] * s;
            bq[q]  = b1[row] * s;
        } else if (layer == 1) {
            int row = 2 * q + unit;
            wa0[q] = W2ih[2 * row + 0] * s;
            wa1[q] = W2ih[2 * row + 1] * s;
            who[q] = W2hh[2 * row + unit] * s;
            whs[q] = W2hh[2 * row + (1 - unit)] * s;
            bq[q]  = b2[row] * s;
        } else {
            wa0[q] = W3ih[2 * q + 0] * s;
            wa1[q] = W3ih[2 * q + 1] * s;
            who[q] = W3hh[q] * s;
            whs[q] = 0.f;
            bq[q]  = b3[q] * s;
        }
    }

    float am0 = 1.f, am1 = 1.f;
    if (layer == 1) { am0 = m1[2 * e + 0]; am1 = m1[2 * e + 1]; }
    if (layer == 2) { am0 = m2[2 * e + 0]; am1 = m2[2 * e + 1]; }
    const float m30 = m3[e];

    // ---- state ----
    float h = 0.f, c = 0.f;
    float hs = 0.f;
    float rin0 = 0.f, rin1 = 0.f;

    const float* xp = x + e;
    const long long Bs = (long long)B;
    const unsigned FULL = 0xffffffffu;

    // uniform scalar step; shfl-dependent operands (hs, a1, a0) outermost,
    // own-h innermost so the post-shfl path is short.
    auto stepU = [&](float a0, float a1, float& nh, float& nc) {
        float g0 = fmaf(hs, whs[0], fmaf(a1, wa1[0], fmaf(a0, wa0[0], fmaf(h, who[0], bq[0]))));
        float g1 = fmaf(hs, whs[1], fmaf(a1, wa1[1], fmaf(a0, wa0[1], fmaf(h, who[1], bq[1]))));
        float g2 = fmaf(hs, whs[2], fmaf(a1, wa1[2], fmaf(a0, wa0[2], fmaf(h, who[2], bq[2]))));
        float g3 = fmaf(hs, whs[3], fmaf(a1, wa1[3], fmaf(a0, wa0[3], fmaf(h, who[3], bq[3]))));
        float t0 = ftanh(g0), t1 = ftanh(g1), t2 = ftanh(g2), t3 = ftanh(g3);
        float ig = fmaf(t0, 0.5f, 0.5f);
        float fg = fmaf(t1, 0.5f, 0.5f);
        float og = fmaf(t3, 0.5f, 0.5f);
        nc = fmaf(fg, c, ig * t2);
        nh = og * ftanh(nc);
    };

    auto exch = [&]() {
        float s_sib = __shfl_sync(FULL, h, sibsrc);
        float s_p0  = __shfl_sync(FULL, h, p0src);
        float s_p1  = __shfl_sync(FULL, h, p1src);
        hs = s_sib;
        rin0 = s_p0;
        rin1 = s_p1;
    };

    // ---- prologue u = 0 ----
    {
        float xk = xp[0];
        float a0 = (layer == 0) ? xk : rin0 * am0;
        float a1 = rin1 * am1;
        float nh, nc;
        stepU(a0, a1, nh, nc);
        if (layer == 0) { h = nh; c = nc; }
        exch();
    }
    // ---- prologue u = 1 ----
    {
        float xk = xp[Bs];
        float a0 = (layer == 0) ? xk : rin0 * am0;
        float a1 = rin1 * am1;
        float nh, nc;
        stepU(a0, a1, nh, nc);
        if (layer <= 1) { h = nh; c = nc; }
        exch();
    }

    // ---- steady state: u = 2 .. T+1; layer l works time u-l; L3 (sub4) stores u-2 ----
    float xa = xp[2 * Bs], xb = xp[3 * Bs], xc = xp[4 * Bs], xd = xp[5 * Bs];

    const float* xr   = xp + 6 * Bs;          // next prefetch row (u+4 at u=2)
    const float* xlast = xp + (long long)(T - 1) * Bs;
    float* orow = out + e;                    // row (u-2) = 0 at u=2

    int u = 2;

    // Main loop: all prefetch rows (uu+4 <= T-1) valid — no clamp logic.
#define V9_MAIN(XREG)                                                          \
    {                                                                          \
        float nx = *xr; xr += Bs;                                              \
        float a0 = (layer == 0) ? XREG : rin0 * am0;                           \
        float a1 = rin1 * am1;                                                 \
        float nh, nc;                                                          \
        stepU(a0, a1, nh, nc);                                                 \
        h = nh; c = nc;                                                        \
        exch();                                                                \
        if (sub == 4) *orow = h * m30;                                         \
        orow += Bs;                                                            \
        XREG = nx;                                                             \
    }

    for (; u + 3 <= T - 5; u += 4) {
        V9_MAIN(xa)
        V9_MAIN(xb)
        V9_MAIN(xc)
        V9_MAIN(xd)
    }
#undef V9_MAIN

    // Tail: clamped prefetch pointer (few iterations).
    for (; u < T + 2; ++u) {
        const float* xq = (xr > xlast) ? xlast : xr;
        float nx = *xq; xr += Bs;
        float a0 = (layer == 0) ? xa : rin0 * am0;
        float a1 = rin1 * am1;
        float nh, nc;
        stepU(a0, a1, nh, nc);
        h = nh; c = nc;
        exch();
        if (sub == 4) *orow = h * m30;
        orow += Bs;
        xa = xb; xb = xc; xc = xd; xd = nx;
    }
}

extern "C" void kernel_launch(void* const* d_in, const int* in_sizes, int n_in,
                              void* d_out, int out_size)
{
    const float* x    = (const float*)d_in[0];
    const float* W1ih = (const float*)d_in[1];
    const float* W1hh = (const float*)d_in[2];
    const float* b1   = (const float*)d_in[3];
    const float* m1   = (const float*)d_in[4];
    const float* W2ih = (const float*)d_in[5];
    const float* W2hh = (const float*)d_in[6];
    const float* b2   = (const float*)d_in[7];
    const float* m2   = (const float*)d_in[8];
    const float* W3ih = (const float*)d_in[9];
    const float* W3hh = (const float*)d_in[10];
    const float* b3   = (const float*)d_in[11];
    const float* m3   = (const float*)d_in[12];

    int B = in_sizes[12];            // m3 is [B]
    int T = in_sizes[0] / B;         // x is [T, B, 1]

    // 6 elements per warp (5 lanes each; lanes 30,31 clamped extras).
    int warps   = (B + 5) / 6;
    int threads = 128;               // 4 warps per block
    int blocks  = (warps + 3) / 4;
    vdlstm_v9_kernel<<<blocks, threads>>>(x, W1ih, W1hh, b1, m1,
                                          W2ih, W2hh, b2, m2,
                                          W3ih, W3hh, b3, m3,
                                          (float*)d_out, T, B);
}

// round 14
// speedup vs baseline: 1.6796x; 1.0025x over previous
#include <cuda_runtime.h>

// VDDecoder: 3-layer LSTM stack (H=2,2,1), locked dropout between layers.
// R14 = R13 (one hidden unit per lane; 5-lane groups L1u0,L1u1,L2u0,L2u1,L3;
// uniform scalar step; pointer-bumped addressing) with:
//  * 2-deep inter-layer stagger: layer l processes time u-2l; prev-layer h
//    arrives through a depth-2 receive FIFO (rA <- rB <- shfl), so the
//    inter-layer shfl latency is hidden by a full iteration.
//  * dropout masks folded into per-lane input weights (each lane = 1 element).
//  * gate fmaf ordered oldest-operand-innermost (own h outermost).

__device__ __forceinline__ float ftanh(float x) {
    float r; asm("tanh.approx.f32 %0, %1;" : "=f"(r) : "f"(x)); return r;
}

extern "C" __global__ void __launch_bounds__(128, 1)
vdlstm_v10_kernel(const float* __restrict__ x,
                  const float* __restrict__ W1ih, const float* __restrict__ W1hh,
                  const float* __restrict__ b1,   const float* __restrict__ m1,
                  const float* __restrict__ W2ih, const float* __restrict__ W2hh,
                  const float* __restrict__ b2,   const float* __restrict__ m2,
                  const float* __restrict__ W3ih, const float* __restrict__ W3hh,
                  const float* __restrict__ b3,   const float* __restrict__ m3,
                  float* __restrict__ out, int T, int B)
{
    const int lane = threadIdx.x & 31;
    const int gw   = blockIdx.x * (blockDim.x >> 5) + (threadIdx.x >> 5);
    const int grp  = lane / 5;                  // 0..6 (grp 6 = lanes 30,31)
    const int sub  = lane - grp * 5;            // 0..4 role
    const int base = grp * 5;
    int e = gw * 6 + grp;
    if (e > B - 1) e = B - 1;

    const int layer = (sub <= 1) ? 0 : (sub <= 3) ? 1 : 2;
    const int unit  = (sub == 1 || sub == 3) ? 1 : 0;

    const int sibsrc = (sub == 4) ? lane : (base + (sub ^ 1));
    const int p0src  = (layer == 2) ? (base + 2) : base;
    const int p1src  = (layer == 2) ? (base + 3) : (base + 1);

    // ---- per-lane scalar weights: 4 gates (q: 0=i 1=f 2=g 3=o) ----
    float wa0[4], wa1[4], who[4], whs[4], bq[4];
#pragma unroll
    for (int q = 0; q < 4; q++) {
        float s = (q == 2) ? 1.0f : 0.5f;
        if (layer == 0) {
            int row = 2 * q + unit;
            wa0[q] = W1ih[row] * s;
            wa1[q] = 0.f;
            who[q] = W1hh[2 * row + unit] * s;
            whs[q] = W1hh[2 * row + (1 - unit)] * s;
            bq[q]  = b1[row] * s;
        } else if (layer == 1) {
            int row = 2 * q + unit;
            wa0[q] = W2ih[2 * row + 0] * s;
            wa1[q] = W2ih[2 * row + 1] * s;
            who[q] = W2hh[2 * row + unit] * s;
            whs[q] = W2hh[2 * row + (1 - unit)] * s;
            bq[q]  = b2[row] * s;
        } else {
            wa0[q] = W3ih[2 * q + 0] * s;
            wa1[q] = W3ih[2 * q + 1] * s;
            who[q] = W3hh[q] * s;
            whs[q] = 0.f;
            bq[q]  = b3[q] * s;
        }
    }

    // ---- fold input dropout masks into input-weight columns ----
    {
        float am0 = 1.f, am1 = 1.f;
        if (layer == 1) { am0 = m1[2 * e + 0]; am1 = m1[2 * e + 1]; }
        if (layer == 2) { am0 = m2[2 * e + 0]; am1 = m2[2 * e + 1]; }
#pragma unroll
        for (int q = 0; q < 4; q++) { wa0[q] *= am0; wa1[q] *= am1; }
    }
    const float m30 = m3[e];

    // ---- state ----
    float h = 0.f, c = 0.f;
    float hs = 0.f;                        // sibling h (1-iter old)
    float rA0 = 0.f, rA1 = 0.f;            // prev-layer h pair to consume now
    float rB0 = 0.f, rB1 = 0.f;            // prev-layer h pair received last exch

    const float* xp = x + e;
    const long long Bs = (long long)B;
    const unsigned FULL = 0xffffffffu;

    // uniform scalar step; oldest operands innermost, own h outermost
    auto stepU = [&](float a0, float a1, float& nh, float& nc) {
        float g0 = fmaf(h, who[0], fmaf(hs, whs[0], fmaf(a1, wa1[0], fmaf(a0, wa0[0], bq[0]))));
        float g1 = fmaf(h, who[1], fmaf(hs, whs[1], fmaf(a1, wa1[1], fmaf(a0, wa0[1], bq[1]))));
        float g2 = fmaf(h, who[2], fmaf(hs, whs[2], fmaf(a1, wa1[2], fmaf(a0, wa0[2], bq[2]))));
        float g3 = fmaf(h, who[3], fmaf(hs, whs[3], fmaf(a1, wa1[3], fmaf(a0, wa0[3], bq[3]))));
        float t0 = ftanh(g0), t1 = ftanh(g1), t2 = ftanh(g2), t3 = ftanh(g3);
        float ig = fmaf(t0, 0.5f, 0.5f);
        float fg = fmaf(t1, 0.5f, 0.5f);
        float og = fmaf(t3, 0.5f, 0.5f);
        nc = fmaf(fg, c, ig * t2);
        nh = og * ftanh(nc);
    };

    // exchange + FIFO rotate
    auto exch = [&]() {
        float s_sib = __shfl_sync(FULL, h, sibsrc);
        float s_p0  = __shfl_sync(FULL, h, p0src);
        float s_p1  = __shfl_sync(FULL, h, p1src);
        hs  = s_sib;
        rA0 = rB0; rA1 = rB1;
        rB0 = s_p0; rB1 = s_p1;
    };

    // ---- prologue: u = 0..3; layer l first commits at u = 2l ----
    for (int u = 0; u < 4; ++u) {
        float xcur = xp[(long long)u * Bs];
        float a0 = (layer == 0) ? xcur : rA0;
        float a1 = rA1;
        float nh, nc;
        stepU(a0, a1, nh, nc);
        if (u >= 2 * layer) { h = nh; c = nc; }
        exch();
    }

    // ---- steady state: u = 4 .. T+3; layer l works time u-2l; L3 stores row u-4 ----
    float xa = xp[4 * Bs], xb = xp[5 * Bs], xc = xp[6 * Bs], xd = xp[7 * Bs];

    const float* xr    = xp + 8 * Bs;                 // prefetch row u+4 (u=4)
    const float* xlast = xp + (long long)(T - 1) * Bs;
    float* orow = out + e;                            // row u-4 = 0 at u=4

    int u = 4;

#define V10_MAIN(XREG)                                                         \
    {                                                                          \
        float nx = *xr; xr += Bs;                                              \
        float a0 = (layer == 0) ? XREG : rA0;                                  \
        float a1 = rA1;                                                        \
        float nh, nc;                                                          \
        stepU(a0, a1, nh, nc);                                                 \
        h = nh; c = nc;                                                        \
        exch();                                                                \
        if (sub == 4) *orow = h * m30;                                         \
        orow += Bs;                                                            \
        XREG = nx;                                                             \
    }

    // main loop: prefetch row u+4 <= T-1 (no clamp logic)
    for (; u + 3 <= T - 5; u += 4) {
        V10_MAIN(xa)
        V10_MAIN(xb)
        V10_MAIN(xc)
        V10_MAIN(xd)
    }
#undef V10_MAIN

    // tail: clamped prefetch; runs through u = T+3 (emits rows .. T-1)
    for (; u < T + 4; ++u) {
        const float* xq = (xr > xlast) ? xlast : xr;
        float nx = *xq; xr += Bs;
        float a0 = (layer == 0) ? xa : rA0;
        float a1 = rA1;
        float nh, nc;
        stepU(a0, a1, nh, nc);
        h = nh; c = nc;
        exch();
        if (sub == 4) *orow = h * m30;
        orow += Bs;
        xa = xb; xb = xc; xc = xd; xd = nx;
    }
}

extern "C" void kernel_launch(void* const* d_in, const int* in_sizes, int n_in,
                              void* d_out, int out_size)
{
    const float* x    = (const float*)d_in[0];
    const float* W1ih = (const float*)d_in[1];
    const float* W1hh = (const float*)d_in[2];
    const float* b1   = (const float*)d_in[3];
    const float* m1   = (const float*)d_in[4];
    const float* W2ih = (const float*)d_in[5];
    const float* W2hh = (const float*)d_in[6];
    const float* b2   = (const float*)d_in[7];
    const float* m2   = (const float*)d_in[8];
    const float* W3ih = (const float*)d_in[9];
    const float* W3hh = (const float*)d_in[10];
    const float* b3   = (const float*)d_in[11];
    const float* m3   = (const float*)d_in[12];

    int B = in_sizes[12];            // m3 is [B]
    int T = in_sizes[0] / B;         // x is [T, B, 1]

    // 6 elements per warp (5 lanes each; lanes 30,31 clamped extras).
    int warps   = (B + 5) / 6;
    int threads = 128;               // 4 warps per block
    int blocks  = (warps + 3) / 4;
    vdlstm_v10_kernel<<<blocks, threads>>>(x, W1ih, W1hh, b1, m1,
                                           W2ih, W2hh, b2, m2,
                                           W3ih, W3hh, b3, m3,
                                           (float*)d_out, T, B);
}

// round 15
// speedup vs baseline: 1.7160x; 1.0217x over previous
#include <cuda_runtime.h>

// VDDecoder: 3-layer LSTM stack (H=2,2,1), locked dropout between layers.
// R15 = R14 (one hidden unit per lane; 5-lane groups L1u0,L1u1,L2u0,L2u1,L3;
// 2-deep inter-layer stagger; masks folded into input weights; pointer-bumped
// addressing) with:
//  * block=64 (2 warps) so SM block distribution caps at 2.5 warps/SMSP
//    instead of 3 (laggard SMSPs set the wall).
//  * gate pre-activations packed as f32x2 pairs: 8 ffma2 instead of 16 ffma.

typedef unsigned long long u64;

__device__ __forceinline__ float ftanh(float x) {
    float r; asm("tanh.approx.f32 %0, %1;" : "=f"(r) : "f"(x)); return r;
}
__device__ __forceinline__ u64 fpk(float lo, float hi) {
    u64 d; asm("mov.b64 %0, {%1, %2};" : "=l"(d) : "f"(lo), "f"(hi)); return d;
}
__device__ __forceinline__ u64 fpk2(float v) { return fpk(v, v); }
__device__ __forceinline__ void funp(u64 v, float& lo, float& hi) {
    asm("mov.b64 {%0, %1}, %2;" : "=f"(lo), "=f"(hi) : "l"(v));
}
__device__ __forceinline__ u64 ffma2(u64 a, u64 b, u64 c) {
    u64 d; asm("fma.rn.f32x2 %0, %1, %2, %3;" : "=l"(d) : "l"(a), "l"(b), "l"(c)); return d;
}

extern "C" __global__ void __launch_bounds__(64, 1)
vdlstm_v11_kernel(const float* __restrict__ x,
                  const float* __restrict__ W1ih, const float* __restrict__ W1hh,
                  const float* __restrict__ b1,   const float* __restrict__ m1,
                  const float* __restrict__ W2ih, const float* __restrict__ W2hh,
                  const float* __restrict__ b2,   const float* __restrict__ m2,
                  const float* __restrict__ W3ih, const float* __restrict__ W3hh,
                  const float* __restrict__ b3,   const float* __restrict__ m3,
                  float* __restrict__ out, int T, int B)
{
    const int lane = threadIdx.x & 31;
    const int gw   = blockIdx.x * (blockDim.x >> 5) + (threadIdx.x >> 5);
    const int grp  = lane / 5;                  // 0..6 (grp 6 = lanes 30,31)
    const int sub  = lane - grp * 5;            // 0..4 role
    const int base = grp * 5;
    int e = gw * 6 + grp;
    if (e > B - 1) e = B - 1;

    const int layer = (sub <= 1) ? 0 : (sub <= 3) ? 1 : 2;
    const int unit  = (sub == 1 || sub == 3) ? 1 : 0;

    const int sibsrc = (sub == 4) ? lane : (base + (sub ^ 1));
    const int p0src  = (layer == 2) ? (base + 2) : base;
    const int p1src  = (layer == 2) ? (base + 3) : (base + 1);

    // ---- per-lane scalar weights, then fold masks, then pack gate pairs ----
    float wa0[4], wa1[4], who[4], whs[4], bq[4];
#pragma unroll
    for (int q = 0; q < 4; q++) {
        float s = (q == 2) ? 1.0f : 0.5f;
        if (layer == 0) {
            int row = 2 * q + unit;
            wa0[q] = W1ih[row] * s;
            wa1[q] = 0.f;
            who[q] = W1hh[2 * row + unit] * s;
            whs[q] = W1hh[2 * row + (1 - unit)] * s;
            bq[q]  = b1[row] * s;
        } else if (layer == 1) {
            int row = 2 * q + unit;
            wa0[q] = W2ih[2 * row + 0] * s;
            wa1[q] = W2ih[2 * row + 1] * s;
            who[q] = W2hh[2 * row + unit] * s;
            whs[q] = W2hh[2 * row + (1 - unit)] * s;
            bq[q]  = b2[row] * s;
        } else {
            wa0[q] = W3ih[2 * q + 0] * s;
            wa1[q] = W3ih[2 * q + 1] * s;
            who[q] = W3hh[q] * s;
            whs[q] = 0.f;
            bq[q]  = b3[q] * s;
        }
    }
    {
        float am0 = 1.f, am1 = 1.f;
        if (layer == 1) { am0 = m1[2 * e + 0]; am1 = m1[2 * e + 1]; }
        if (layer == 2) { am0 = m2[2 * e + 0]; am1 = m2[2 * e + 1]; }
#pragma unroll
        for (int q = 0; q < 4; q++) { wa0[q] *= am0; wa1[q] *= am1; }
    }
    const float m30 = m3[e];

    // packed weights: pair P covers gates (2P, 2P+1)
    u64 Pa0[2], Pa1[2], Pho[2], Phs[2], Pb[2];
#pragma unroll
    for (int P = 0; P < 2; P++) {
        Pa0[P] = fpk(wa0[2 * P], wa0[2 * P + 1]);
        Pa1[P] = fpk(wa1[2 * P], wa1[2 * P + 1]);
        Pho[P] = fpk(who[2 * P], who[2 * P + 1]);
        Phs[P] = fpk(whs[2 * P], whs[2 * P + 1]);
        Pb[P]  = fpk(bq[2 * P],  bq[2 * P + 1]);
    }

    // ---- state ----
    float h = 0.f, c = 0.f;
    float hs = 0.f;                        // sibling h (1-iter old)
    float rA0 = 0.f, rA1 = 0.f;            // prev-layer pair to consume now
    float rB0 = 0.f, rB1 = 0.f;            // received last exch

    const float* xp = x + e;
    const long long Bs = (long long)B;
    const unsigned FULL = 0xffffffffu;

    // uniform scalar step, gates packed f32x2
    auto stepU = [&](float a0, float a1, float& nh, float& nc) {
        u64 a0b = fpk2(a0), a1b = fpk2(a1), hb = fpk2(h), hsb = fpk2(hs);
        u64 gP0 = ffma2(hb, Pho[0], ffma2(hsb, Phs[0], ffma2(a1b, Pa1[0], ffma2(a0b, Pa0[0], Pb[0]))));
        u64 gP1 = ffma2(hb, Pho[1], ffma2(hsb, Phs[1], ffma2(a1b, Pa1[1], ffma2(a0b, Pa0[1], Pb[1]))));
        float g0, g1, g2, g3;
        funp(gP0, g0, g1);
        funp(gP1, g2, g3);
        float t0 = ftanh(g0), t1 = ftanh(g1), t2 = ftanh(g2), t3 = ftanh(g3);
        float ig = fmaf(t0, 0.5f, 0.5f);
        float fg = fmaf(t1, 0.5f, 0.5f);
        float og = fmaf(t3, 0.5f, 0.5f);
        nc = fmaf(fg, c, ig * t2);
        nh = og * ftanh(nc);
    };

    auto exch = [&]() {
        float s_sib = __shfl_sync(FULL, h, sibsrc);
        float s_p0  = __shfl_sync(FULL, h, p0src);
        float s_p1  = __shfl_sync(FULL, h, p1src);
        hs  = s_sib;
        rA0 = rB0; rA1 = rB1;
        rB0 = s_p0; rB1 = s_p1;
    };

    // ---- prologue: u = 0..3; layer l first commits at u = 2l ----
    for (int u = 0; u < 4; ++u) {
        float xcur = xp[(long long)u * Bs];
        float a0 = (layer == 0) ? xcur : rA0;
        float a1 = rA1;
        float nh, nc;
        stepU(a0, a1, nh, nc);
        if (u >= 2 * layer) { h = nh; c = nc; }
        exch();
    }

    // ---- steady state: u = 4 .. T+3; layer l works time u-2l; L3 stores row u-4 ----
    float xa = xp[4 * Bs], xb = xp[5 * Bs], xc = xp[6 * Bs], xd = xp[7 * Bs];

    const float* xr    = xp + 8 * Bs;                 // prefetch row u+4 (u=4)
    const float* xlast = xp + (long long)(T - 1) * Bs;
    float* orow = out + e;                            // row u-4 = 0 at u=4

    int u = 4;

#define V11_MAIN(XREG)                                                         \
    {                                                                          \
        float nx = *xr; xr += Bs;                                              \
        float a0 = (layer == 0) ? XREG : rA0;                                  \
        float a1 = rA1;                                                        \
        float nh, nc;                                                          \
        stepU(a0, a1, nh, nc);                                                 \
        h = nh; c = nc;                                                        \
        exch();                                                                \
        if (sub == 4) *orow = h * m30;                                         \
        orow += Bs;                                                            \
        XREG = nx;                                                             \
    }

    for (; u + 3 <= T - 5; u += 4) {
        V11_MAIN(xa)
        V11_MAIN(xb)
        V11_MAIN(xc)
        V11_MAIN(xd)
    }
#undef V11_MAIN

    // tail: clamped prefetch; runs through u = T+3 (emits rows .. T-1)
    for (; u < T + 4; ++u) {
        const float* xq = (xr > xlast) ? xlast : xr;
        float nx = *xq; xr += Bs;
        float a0 = (layer == 0) ? xa : rA0;
        float a1 = rA1;
        float nh, nc;
        stepU(a0, a1, nh, nc);
        h = nh; c = nc;
        exch();
        if (sub == 4) *orow = h * m30;
        orow += Bs;
        xa = xb; xb = xc; xc = xd; xd = nx;
    }
}

extern "C" void kernel_launch(void* const* d_in, const int* in_sizes, int n_in,
                              void* d_out, int out_size)
{
    const float* x    = (const float*)d_in[0];
    const float* W1ih = (const float*)d_in[1];
    const float* W1hh = (const float*)d_in[2];
    const float* b1   = (const float*)d_in[3];
    const float* m1   = (const float*)d_in[4];
    const float* W2ih = (const float*)d_in[5];
    const float* W2hh = (const float*)d_in[6];
    const float* b2   = (const float*)d_in[7];
    const float* m2   = (const float*)d_in[8];
    const float* W3ih = (const float*)d_in[9];
    const float* W3hh = (const float*)d_in[10];
    const float* b3   = (const float*)d_in[11];
    const float* m3   = (const float*)d_in[12];

    int B = in_sizes[12];            // m3 is [B]
    int T = in_sizes[0] / B;         // x is [T, B, 1]

    // 6 elements per warp; block = 2 warps (12 elements) for finer-grained
    // block distribution across SMs (caps laggard SMSPs at 2.5 warps).
    int warps   = (B + 5) / 6;
    int threads = 64;
    int blocks  = (warps + 1) / 2;
    vdlstm_v11_kernel<<<blocks, threads>>>(x, W1ih, W1hh, b1, m1,
                                           W2ih, W2hh, b2, m2,
                                           W3ih, W3hh, b3, m3,
                                           (float*)d_out, T, B);
}